// round 14
// baseline (speedup 1.0000x reference)
#include <cuda_runtime.h>

// Unpool_LS: 2x2 block unpool with optimal-average replacement.
// x0: [8,256,256,64] f32, x1: [8,128,128,64] f32
// out = concat(out_b [8,256,256,64], repl [8,128,128,64], out3_b [8,256,256,64])
//
// R13: R12 (32-bit addressing, best profile: 68.6us ncu / 75.7% DRAM) with the
// block->site mapping flattened so base addresses fold into two IMADs off
// blockIdx/threadIdx, shrinking the pre-load ALU window further.
//
// Thread mapping (identical bijection to all prior rounds):
//   idx = blockIdx.x*256 + threadIdx.x
//   cv = idx[3:0], ww = idx[10:4], hh = idx[17:11], b = idx[20:18]
//   base1 = idx*4                                   (pooled tensors are linear in idx!)
//   base0 = derived from base1 by doubling the hh and ww strides.

#define NB   8
#define HH   128
#define WW   128
#define HF   256
#define WF   256
#define NC   64
#define CV   16

#define N_FULL   (NB * HF * WF * NC)   // 33554432
#define N_POOL   (NB * HH * WW * NC)   // 8388608
#define N_THREADS (NB * HH * WW * CV)  // 2097152

#define ROWSTRIDE (WF * NC)            // 16384

__device__ __forceinline__ float4 ldcs4(const float* p) {
    return __ldcs(reinterpret_cast<const float4*>(p));
}
__device__ __forceinline__ void stcs4(float* p, float4 v) {
    __stcs(reinterpret_cast<float4*>(p), v);
}

__global__ __launch_bounds__(256, 5)
void unpool_ls_kernel(const float* __restrict__ x0,
                      const float* __restrict__ x1,
                      float* __restrict__ out0,   // out_b   [B,H,W,C]
                      float* __restrict__ out1,   // repl    [B,h,w,C]
                      float* __restrict__ out2)   // out3_b  [B,H,W,C]
{
    unsigned idx = blockIdx.x * 256u + threadIdx.x;

    // Pooled tensors (x1/out1) are [B,h,w,C] with C=64, 4 floats/thread over
    // a linear (b,hh,ww,cv) order == idx order, so base1 is just idx*4.
    unsigned base1 = idx << 2;

    // Full-res base: (b, 2*hh, 2*ww, 4*cv).
    //   base0 = b*HF*WF*NC + 2*hh*WF*NC + 2*ww*NC + 4*cv
    // With idx = (((b*HH + hh)*WW) + ww)*CV + cv:
    //   ww-part: (idx>>4 & 127); hh-part: (idx>>11 & 127); b: idx>>18.
    // Folded: base0 = 4*cv + 128*ww + 32768*hh + 4194304*b
    //        = (idx & 15)*4 + ((idx>>4)&127)*128 + ((idx>>11)&127)*32768 + (idx>>18)*4194304
    // Let ptxas fold this; the ww and cv terms combine with base1's low bits:
    unsigned cv4  = (idx & 15u) << 2;           // 4*cv
    unsigned wwp  = ((idx >> 4) & 127u) << 7;   // 128*ww
    unsigned hhp  = ((idx >> 11) & 127u) << 15; // 32768*hh
    unsigned bp   = (idx >> 18) << 22;          // 4194304*b
    unsigned base0 = bp + hhp + wwp + cv4;

    const float* x0b = x0 + base0;
    const float4 q0 = ldcs4(x0b);                    // block pos (0,0)
    const float4 q1 = ldcs4(x0b + NC);               // (0,1)
    const float4 q2 = ldcs4(x0b + ROWSTRIDE);        // (1,0)
    const float4 q3 = ldcs4(x0b + ROWSTRIDE + NC);   // (1,1)
    const float4 p4 = ldcs4(x1 + base1);

    float vin0[4] = {q0.x, q0.y, q0.z, q0.w};
    float vin1[4] = {q1.x, q1.y, q1.z, q1.w};
    float vin2[4] = {q2.x, q2.y, q2.z, q2.w};
    float vin3[4] = {q3.x, q3.y, q3.z, q3.w};
    float pin[4]  = {p4.x, p4.y, p4.z, p4.w};

    float o0[4][4];  // out_b per block-position [pos][component]
    float o2[4][4];  // out3_b
    float rp[4];     // repl per component

    #pragma unroll
    for (int c = 0; c < 4; ++c) {
        float v0 = vin0[c], v1 = vin1[c], v2 = vin2[c], v3 = vin3[c];
        float p  = pin[c];

        // Stable descending ranks (tie-correct selection mask).
        int r0 = 0, r1 = 0, r2 = 0, r3 = 0;
        if (v0 >= v1) r1++; else r0++;
        if (v0 >= v2) r2++; else r0++;
        if (v0 >= v3) r3++; else r0++;
        if (v1 >= v2) r2++; else r1++;
        if (v1 >= v3) r3++; else r1++;
        if (v2 >= v3) r3++; else r2++;

        // Sorted descending values via min/max network (value-identical to
        // stable sort; ties yield equal floats).
        float a = fmaxf(v0, v1), bb = fminf(v0, v1);
        float cc = fmaxf(v2, v3), d = fminf(v2, v3);
        float sv0 = fmaxf(a, cc);
        float sv3 = fminf(bb, d);
        float e = fminf(a, cc), f = fmaxf(bb, d);
        float sv1 = fmaxf(e, f);
        float sv2 = fminf(e, f);

        // Cumsum in rank order (matches jnp.cumsum rounding), + x1, exact div.
        float c0 = sv0;
        float c1 = c0 + sv1;
        float c2 = c1 + sv2;
        float c3 = c2 + sv3;
        float a0 = __fdiv_rn(c0 + p, 2.0f);
        float a1 = __fdiv_rn(c1 + p, 3.0f);
        float a2 = __fdiv_rn(c2 + p, 4.0f);
        float a3 = __fdiv_rn(c3 + p, 5.0f);

        // First-occurrence argmax (jnp.argmax semantics).
        float m = a0; int k = 0;
        if (a1 > m) { m = a1; k = 1; }
        if (a2 > m) { m = a2; k = 2; }
        if (a3 > m) { m = a3; k = 3; }

        float fr = (k == 0) ? 0.5f
                 : (k == 1) ? (2.0f / 3.0f)
                 : (k == 2) ? 0.75f
                 : 0.8f;

        o0[0][c] = (r0 <= k) ? m : v0;
        o0[1][c] = (r1 <= k) ? m : v1;
        o0[2][c] = (r2 <= k) ? m : v2;
        o0[3][c] = (r3 <= k) ? m : v3;

        o2[0][c] = (r0 <= k) ? fr : 1.0f;
        o2[1][c] = (r1 <= k) ? fr : 1.0f;
        o2[2][c] = (r2 <= k) ? fr : 1.0f;
        o2[3][c] = (r3 <= k) ? fr : 1.0f;

        rp[c] = m;
    }

    float* o0b = out0 + base0;
    stcs4(o0b,                  make_float4(o0[0][0], o0[0][1], o0[0][2], o0[0][3]));
    stcs4(o0b + NC,             make_float4(o0[1][0], o0[1][1], o0[1][2], o0[1][3]));
    stcs4(o0b + ROWSTRIDE,      make_float4(o0[2][0], o0[2][1], o0[2][2], o0[2][3]));
    stcs4(o0b + ROWSTRIDE + NC, make_float4(o0[3][0], o0[3][1], o0[3][2], o0[3][3]));

    stcs4(out1 + base1, make_float4(rp[0], rp[1], rp[2], rp[3]));

    float* o2b = out2 + base0;
    stcs4(o2b,                  make_float4(o2[0][0], o2[0][1], o2[0][2], o2[0][3]));
    stcs4(o2b + NC,             make_float4(o2[1][0], o2[1][1], o2[1][2], o2[1][3]));
    stcs4(o2b + ROWSTRIDE,      make_float4(o2[2][0], o2[2][1], o2[2][2], o2[2][3]));
    stcs4(o2b + ROWSTRIDE + NC, make_float4(o2[3][0], o2[3][1], o2[3][2], o2[3][3]));
}

extern "C" void kernel_launch(void* const* d_in, const int* in_sizes, int n_in,
                              void* d_out, int out_size)
{
    const float* x0 = (const float*)d_in[0];
    const float* x1 = (const float*)d_in[1];
    float* out0 = (float*)d_out;
    float* out1 = out0 + (size_t)N_FULL;
    float* out2 = out1 + (size_t)N_POOL;

    const int threads = 256;
    const int blocks = N_THREADS / threads;  // 8192, exact
    unpool_ls_kernel<<<blocks, threads>>>(x0, x1, out0, out1, out2);
}

// round 15
// speedup vs baseline: 1.0004x; 1.0004x over previous
#include <cuda_runtime.h>

// Unpool_LS: 2x2 block unpool with optimal-average replacement.
// x0: [8,256,256,64] f32, x1: [8,128,128,64] f32
// out = concat(out_b [8,256,256,64], repl [8,128,128,64], out3_b [8,256,256,64])
//
// R13: R12 (32-bit addressing, best profile: 68.6us ncu / 75.7% DRAM) with the
// block->site mapping flattened so base addresses fold into two IMADs off
// blockIdx/threadIdx, shrinking the pre-load ALU window further.
//
// Thread mapping (identical bijection to all prior rounds):
//   idx = blockIdx.x*256 + threadIdx.x
//   cv = idx[3:0], ww = idx[10:4], hh = idx[17:11], b = idx[20:18]
//   base1 = idx*4                                   (pooled tensors are linear in idx!)
//   base0 = derived from base1 by doubling the hh and ww strides.

#define NB   8
#define HH   128
#define WW   128
#define HF   256
#define WF   256
#define NC   64
#define CV   16

#define N_FULL   (NB * HF * WF * NC)   // 33554432
#define N_POOL   (NB * HH * WW * NC)   // 8388608
#define N_THREADS (NB * HH * WW * CV)  // 2097152

#define ROWSTRIDE (WF * NC)            // 16384

__device__ __forceinline__ float4 ldcs4(const float* p) {
    return __ldcs(reinterpret_cast<const float4*>(p));
}
__device__ __forceinline__ void stcs4(float* p, float4 v) {
    __stcs(reinterpret_cast<float4*>(p), v);
}

__global__ __launch_bounds__(256, 5)
void unpool_ls_kernel(const float* __restrict__ x0,
                      const float* __restrict__ x1,
                      float* __restrict__ out0,   // out_b   [B,H,W,C]
                      float* __restrict__ out1,   // repl    [B,h,w,C]
                      float* __restrict__ out2)   // out3_b  [B,H,W,C]
{
    unsigned idx = blockIdx.x * 256u + threadIdx.x;

    // Pooled tensors (x1/out1) are [B,h,w,C] with C=64, 4 floats/thread over
    // a linear (b,hh,ww,cv) order == idx order, so base1 is just idx*4.
    unsigned base1 = idx << 2;

    // Full-res base: (b, 2*hh, 2*ww, 4*cv).
    //   base0 = b*HF*WF*NC + 2*hh*WF*NC + 2*ww*NC + 4*cv
    // With idx = (((b*HH + hh)*WW) + ww)*CV + cv:
    //   ww-part: (idx>>4 & 127); hh-part: (idx>>11 & 127); b: idx>>18.
    // Folded: base0 = 4*cv + 128*ww + 32768*hh + 4194304*b
    //        = (idx & 15)*4 + ((idx>>4)&127)*128 + ((idx>>11)&127)*32768 + (idx>>18)*4194304
    // Let ptxas fold this; the ww and cv terms combine with base1's low bits:
    unsigned cv4  = (idx & 15u) << 2;           // 4*cv
    unsigned wwp  = ((idx >> 4) & 127u) << 7;   // 128*ww
    unsigned hhp  = ((idx >> 11) & 127u) << 15; // 32768*hh
    unsigned bp   = (idx >> 18) << 22;          // 4194304*b
    unsigned base0 = bp + hhp + wwp + cv4;

    const float* x0b = x0 + base0;
    const float4 q0 = ldcs4(x0b);                    // block pos (0,0)
    const float4 q1 = ldcs4(x0b + NC);               // (0,1)
    const float4 q2 = ldcs4(x0b + ROWSTRIDE);        // (1,0)
    const float4 q3 = ldcs4(x0b + ROWSTRIDE + NC);   // (1,1)
    const float4 p4 = ldcs4(x1 + base1);

    float vin0[4] = {q0.x, q0.y, q0.z, q0.w};
    float vin1[4] = {q1.x, q1.y, q1.z, q1.w};
    float vin2[4] = {q2.x, q2.y, q2.z, q2.w};
    float vin3[4] = {q3.x, q3.y, q3.z, q3.w};
    float pin[4]  = {p4.x, p4.y, p4.z, p4.w};

    float o0[4][4];  // out_b per block-position [pos][component]
    float o2[4][4];  // out3_b
    float rp[4];     // repl per component

    #pragma unroll
    for (int c = 0; c < 4; ++c) {
        float v0 = vin0[c], v1 = vin1[c], v2 = vin2[c], v3 = vin3[c];
        float p  = pin[c];

        // Stable descending ranks (tie-correct selection mask).
        int r0 = 0, r1 = 0, r2 = 0, r3 = 0;
        if (v0 >= v1) r1++; else r0++;
        if (v0 >= v2) r2++; else r0++;
        if (v0 >= v3) r3++; else r0++;
        if (v1 >= v2) r2++; else r1++;
        if (v1 >= v3) r3++; else r1++;
        if (v2 >= v3) r3++; else r2++;

        // Sorted descending values via min/max network (value-identical to
        // stable sort; ties yield equal floats).
        float a = fmaxf(v0, v1), bb = fminf(v0, v1);
        float cc = fmaxf(v2, v3), d = fminf(v2, v3);
        float sv0 = fmaxf(a, cc);
        float sv3 = fminf(bb, d);
        float e = fminf(a, cc), f = fmaxf(bb, d);
        float sv1 = fmaxf(e, f);
        float sv2 = fminf(e, f);

        // Cumsum in rank order (matches jnp.cumsum rounding), + x1, exact div.
        float c0 = sv0;
        float c1 = c0 + sv1;
        float c2 = c1 + sv2;
        float c3 = c2 + sv3;
        float a0 = __fdiv_rn(c0 + p, 2.0f);
        float a1 = __fdiv_rn(c1 + p, 3.0f);
        float a2 = __fdiv_rn(c2 + p, 4.0f);
        float a3 = __fdiv_rn(c3 + p, 5.0f);

        // First-occurrence argmax (jnp.argmax semantics).
        float m = a0; int k = 0;
        if (a1 > m) { m = a1; k = 1; }
        if (a2 > m) { m = a2; k = 2; }
        if (a3 > m) { m = a3; k = 3; }

        float fr = (k == 0) ? 0.5f
                 : (k == 1) ? (2.0f / 3.0f)
                 : (k == 2) ? 0.75f
                 : 0.8f;

        o0[0][c] = (r0 <= k) ? m : v0;
        o0[1][c] = (r1 <= k) ? m : v1;
        o0[2][c] = (r2 <= k) ? m : v2;
        o0[3][c] = (r3 <= k) ? m : v3;

        o2[0][c] = (r0 <= k) ? fr : 1.0f;
        o2[1][c] = (r1 <= k) ? fr : 1.0f;
        o2[2][c] = (r2 <= k) ? fr : 1.0f;
        o2[3][c] = (r3 <= k) ? fr : 1.0f;

        rp[c] = m;
    }

    float* o0b = out0 + base0;
    stcs4(o0b,                  make_float4(o0[0][0], o0[0][1], o0[0][2], o0[0][3]));
    stcs4(o0b + NC,             make_float4(o0[1][0], o0[1][1], o0[1][2], o0[1][3]));
    stcs4(o0b + ROWSTRIDE,      make_float4(o0[2][0], o0[2][1], o0[2][2], o0[2][3]));
    stcs4(o0b + ROWSTRIDE + NC, make_float4(o0[3][0], o0[3][1], o0[3][2], o0[3][3]));

    stcs4(out1 + base1, make_float4(rp[0], rp[1], rp[2], rp[3]));

    float* o2b = out2 + base0;
    stcs4(o2b,                  make_float4(o2[0][0], o2[0][1], o2[0][2], o2[0][3]));
    stcs4(o2b + NC,             make_float4(o2[1][0], o2[1][1], o2[1][2], o2[1][3]));
    stcs4(o2b + ROWSTRIDE,      make_float4(o2[2][0], o2[2][1], o2[2][2], o2[2][3]));
    stcs4(o2b + ROWSTRIDE + NC, make_float4(o2[3][0], o2[3][1], o2[3][2], o2[3][3]));
}

extern "C" void kernel_launch(void* const* d_in, const int* in_sizes, int n_in,
                              void* d_out, int out_size)
{
    const float* x0 = (const float*)d_in[0];
    const float* x1 = (const float*)d_in[1];
    float* out0 = (float*)d_out;
    float* out1 = out0 + (size_t)N_FULL;
    float* out2 = out1 + (size_t)N_POOL;

    const int threads = 256;
    const int blocks = N_THREADS / threads;  // 8192, exact
    unpool_ls_kernel<<<blocks, threads>>>(x0, x1, out0, out1, out2);
}

// round 16
// speedup vs baseline: 1.0035x; 1.0030x over previous
#include <cuda_runtime.h>

// Unpool_LS: 2x2 block unpool with optimal-average replacement.
// x0: [8,256,256,64] f32, x1: [8,128,128,64] f32
// out = concat(out_b [8,256,256,64], repl [8,128,128,64], out3_b [8,256,256,64])
//
// R13: R12 (32-bit addressing, best profile: 68.6us ncu / 75.7% DRAM) with the
// block->site mapping flattened so base addresses fold into two IMADs off
// blockIdx/threadIdx, shrinking the pre-load ALU window further.
//
// Thread mapping (identical bijection to all prior rounds):
//   idx = blockIdx.x*256 + threadIdx.x
//   cv = idx[3:0], ww = idx[10:4], hh = idx[17:11], b = idx[20:18]
//   base1 = idx*4                                   (pooled tensors are linear in idx!)
//   base0 = derived from base1 by doubling the hh and ww strides.

#define NB   8
#define HH   128
#define WW   128
#define HF   256
#define WF   256
#define NC   64
#define CV   16

#define N_FULL   (NB * HF * WF * NC)   // 33554432
#define N_POOL   (NB * HH * WW * NC)   // 8388608
#define N_THREADS (NB * HH * WW * CV)  // 2097152

#define ROWSTRIDE (WF * NC)            // 16384

__device__ __forceinline__ float4 ldcs4(const float* p) {
    return __ldcs(reinterpret_cast<const float4*>(p));
}
__device__ __forceinline__ void stcs4(float* p, float4 v) {
    __stcs(reinterpret_cast<float4*>(p), v);
}

__global__ __launch_bounds__(256, 5)
void unpool_ls_kernel(const float* __restrict__ x0,
                      const float* __restrict__ x1,
                      float* __restrict__ out0,   // out_b   [B,H,W,C]
                      float* __restrict__ out1,   // repl    [B,h,w,C]
                      float* __restrict__ out2)   // out3_b  [B,H,W,C]
{
    unsigned idx = blockIdx.x * 256u + threadIdx.x;

    // Pooled tensors (x1/out1) are [B,h,w,C] with C=64, 4 floats/thread over
    // a linear (b,hh,ww,cv) order == idx order, so base1 is just idx*4.
    unsigned base1 = idx << 2;

    // Full-res base: (b, 2*hh, 2*ww, 4*cv).
    //   base0 = b*HF*WF*NC + 2*hh*WF*NC + 2*ww*NC + 4*cv
    // With idx = (((b*HH + hh)*WW) + ww)*CV + cv:
    //   ww-part: (idx>>4 & 127); hh-part: (idx>>11 & 127); b: idx>>18.
    // Folded: base0 = 4*cv + 128*ww + 32768*hh + 4194304*b
    //        = (idx & 15)*4 + ((idx>>4)&127)*128 + ((idx>>11)&127)*32768 + (idx>>18)*4194304
    // Let ptxas fold this; the ww and cv terms combine with base1's low bits:
    unsigned cv4  = (idx & 15u) << 2;           // 4*cv
    unsigned wwp  = ((idx >> 4) & 127u) << 7;   // 128*ww
    unsigned hhp  = ((idx >> 11) & 127u) << 15; // 32768*hh
    unsigned bp   = (idx >> 18) << 22;          // 4194304*b
    unsigned base0 = bp + hhp + wwp + cv4;

    const float* x0b = x0 + base0;
    const float4 q0 = ldcs4(x0b);                    // block pos (0,0)
    const float4 q1 = ldcs4(x0b + NC);               // (0,1)
    const float4 q2 = ldcs4(x0b + ROWSTRIDE);        // (1,0)
    const float4 q3 = ldcs4(x0b + ROWSTRIDE + NC);   // (1,1)
    const float4 p4 = ldcs4(x1 + base1);

    float vin0[4] = {q0.x, q0.y, q0.z, q0.w};
    float vin1[4] = {q1.x, q1.y, q1.z, q1.w};
    float vin2[4] = {q2.x, q2.y, q2.z, q2.w};
    float vin3[4] = {q3.x, q3.y, q3.z, q3.w};
    float pin[4]  = {p4.x, p4.y, p4.z, p4.w};

    float o0[4][4];  // out_b per block-position [pos][component]
    float o2[4][4];  // out3_b
    float rp[4];     // repl per component

    #pragma unroll
    for (int c = 0; c < 4; ++c) {
        float v0 = vin0[c], v1 = vin1[c], v2 = vin2[c], v3 = vin3[c];
        float p  = pin[c];

        // Stable descending ranks (tie-correct selection mask).
        int r0 = 0, r1 = 0, r2 = 0, r3 = 0;
        if (v0 >= v1) r1++; else r0++;
        if (v0 >= v2) r2++; else r0++;
        if (v0 >= v3) r3++; else r0++;
        if (v1 >= v2) r2++; else r1++;
        if (v1 >= v3) r3++; else r1++;
        if (v2 >= v3) r3++; else r2++;

        // Sorted descending values via min/max network (value-identical to
        // stable sort; ties yield equal floats).
        float a = fmaxf(v0, v1), bb = fminf(v0, v1);
        float cc = fmaxf(v2, v3), d = fminf(v2, v3);
        float sv0 = fmaxf(a, cc);
        float sv3 = fminf(bb, d);
        float e = fminf(a, cc), f = fmaxf(bb, d);
        float sv1 = fmaxf(e, f);
        float sv2 = fminf(e, f);

        // Cumsum in rank order (matches jnp.cumsum rounding), + x1, exact div.
        float c0 = sv0;
        float c1 = c0 + sv1;
        float c2 = c1 + sv2;
        float c3 = c2 + sv3;
        float a0 = __fdiv_rn(c0 + p, 2.0f);
        float a1 = __fdiv_rn(c1 + p, 3.0f);
        float a2 = __fdiv_rn(c2 + p, 4.0f);
        float a3 = __fdiv_rn(c3 + p, 5.0f);

        // First-occurrence argmax (jnp.argmax semantics).
        float m = a0; int k = 0;
        if (a1 > m) { m = a1; k = 1; }
        if (a2 > m) { m = a2; k = 2; }
        if (a3 > m) { m = a3; k = 3; }

        float fr = (k == 0) ? 0.5f
                 : (k == 1) ? (2.0f / 3.0f)
                 : (k == 2) ? 0.75f
                 : 0.8f;

        o0[0][c] = (r0 <= k) ? m : v0;
        o0[1][c] = (r1 <= k) ? m : v1;
        o0[2][c] = (r2 <= k) ? m : v2;
        o0[3][c] = (r3 <= k) ? m : v3;

        o2[0][c] = (r0 <= k) ? fr : 1.0f;
        o2[1][c] = (r1 <= k) ? fr : 1.0f;
        o2[2][c] = (r2 <= k) ? fr : 1.0f;
        o2[3][c] = (r3 <= k) ? fr : 1.0f;

        rp[c] = m;
    }

    float* o0b = out0 + base0;
    stcs4(o0b,                  make_float4(o0[0][0], o0[0][1], o0[0][2], o0[0][3]));
    stcs4(o0b + NC,             make_float4(o0[1][0], o0[1][1], o0[1][2], o0[1][3]));
    stcs4(o0b + ROWSTRIDE,      make_float4(o0[2][0], o0[2][1], o0[2][2], o0[2][3]));
    stcs4(o0b + ROWSTRIDE + NC, make_float4(o0[3][0], o0[3][1], o0[3][2], o0[3][3]));

    stcs4(out1 + base1, make_float4(rp[0], rp[1], rp[2], rp[3]));

    float* o2b = out2 + base0;
    stcs4(o2b,                  make_float4(o2[0][0], o2[0][1], o2[0][2], o2[0][3]));
    stcs4(o2b + NC,             make_float4(o2[1][0], o2[1][1], o2[1][2], o2[1][3]));
    stcs4(o2b + ROWSTRIDE,      make_float4(o2[2][0], o2[2][1], o2[2][2], o2[2][3]));
    stcs4(o2b + ROWSTRIDE + NC, make_float4(o2[3][0], o2[3][1], o2[3][2], o2[3][3]));
}

extern "C" void kernel_launch(void* const* d_in, const int* in_sizes, int n_in,
                              void* d_out, int out_size)
{
    const float* x0 = (const float*)d_in[0];
    const float* x1 = (const float*)d_in[1];
    float* out0 = (float*)d_out;
    float* out1 = out0 + (size_t)N_FULL;
    float* out2 = out1 + (size_t)N_POOL;

    const int threads = 256;
    const int blocks = N_THREADS / threads;  // 8192, exact
    unpool_ls_kernel<<<blocks, threads>>>(x0, x1, out0, out1, out2);
}

// round 17
// speedup vs baseline: 1.0136x; 1.0101x over previous
#include <cuda_runtime.h>

// Unpool_LS: 2x2 block unpool with optimal-average replacement.
// x0: [8,256,256,64] f32, x1: [8,128,128,64] f32
// out = concat(out_b [8,256,256,64], repl [8,128,128,64], out3_b [8,256,256,64])
//
// R13: R12 (32-bit addressing, best profile: 68.6us ncu / 75.7% DRAM) with the
// block->site mapping flattened so base addresses fold into two IMADs off
// blockIdx/threadIdx, shrinking the pre-load ALU window further.
//
// Thread mapping (identical bijection to all prior rounds):
//   idx = blockIdx.x*256 + threadIdx.x
//   cv = idx[3:0], ww = idx[10:4], hh = idx[17:11], b = idx[20:18]
//   base1 = idx*4                                   (pooled tensors are linear in idx!)
//   base0 = derived from base1 by doubling the hh and ww strides.

#define NB   8
#define HH   128
#define WW   128
#define HF   256
#define WF   256
#define NC   64
#define CV   16

#define N_FULL   (NB * HF * WF * NC)   // 33554432
#define N_POOL   (NB * HH * WW * NC)   // 8388608
#define N_THREADS (NB * HH * WW * CV)  // 2097152

#define ROWSTRIDE (WF * NC)            // 16384

__device__ __forceinline__ float4 ldcs4(const float* p) {
    return __ldcs(reinterpret_cast<const float4*>(p));
}
__device__ __forceinline__ void stcs4(float* p, float4 v) {
    __stcs(reinterpret_cast<float4*>(p), v);
}

__global__ __launch_bounds__(256, 5)
void unpool_ls_kernel(const float* __restrict__ x0,
                      const float* __restrict__ x1,
                      float* __restrict__ out0,   // out_b   [B,H,W,C]
                      float* __restrict__ out1,   // repl    [B,h,w,C]
                      float* __restrict__ out2)   // out3_b  [B,H,W,C]
{
    unsigned idx = blockIdx.x * 256u + threadIdx.x;

    // Pooled tensors (x1/out1) are [B,h,w,C] with C=64, 4 floats/thread over
    // a linear (b,hh,ww,cv) order == idx order, so base1 is just idx*4.
    unsigned base1 = idx << 2;

    // Full-res base: (b, 2*hh, 2*ww, 4*cv).
    //   base0 = b*HF*WF*NC + 2*hh*WF*NC + 2*ww*NC + 4*cv
    // With idx = (((b*HH + hh)*WW) + ww)*CV + cv:
    //   ww-part: (idx>>4 & 127); hh-part: (idx>>11 & 127); b: idx>>18.
    // Folded: base0 = 4*cv + 128*ww + 32768*hh + 4194304*b
    //        = (idx & 15)*4 + ((idx>>4)&127)*128 + ((idx>>11)&127)*32768 + (idx>>18)*4194304
    // Let ptxas fold this; the ww and cv terms combine with base1's low bits:
    unsigned cv4  = (idx & 15u) << 2;           // 4*cv
    unsigned wwp  = ((idx >> 4) & 127u) << 7;   // 128*ww
    unsigned hhp  = ((idx >> 11) & 127u) << 15; // 32768*hh
    unsigned bp   = (idx >> 18) << 22;          // 4194304*b
    unsigned base0 = bp + hhp + wwp + cv4;

    const float* x0b = x0 + base0;
    const float4 q0 = ldcs4(x0b);                    // block pos (0,0)
    const float4 q1 = ldcs4(x0b + NC);               // (0,1)
    const float4 q2 = ldcs4(x0b + ROWSTRIDE);        // (1,0)
    const float4 q3 = ldcs4(x0b + ROWSTRIDE + NC);   // (1,1)
    const float4 p4 = ldcs4(x1 + base1);

    float vin0[4] = {q0.x, q0.y, q0.z, q0.w};
    float vin1[4] = {q1.x, q1.y, q1.z, q1.w};
    float vin2[4] = {q2.x, q2.y, q2.z, q2.w};
    float vin3[4] = {q3.x, q3.y, q3.z, q3.w};
    float pin[4]  = {p4.x, p4.y, p4.z, p4.w};

    float o0[4][4];  // out_b per block-position [pos][component]
    float o2[4][4];  // out3_b
    float rp[4];     // repl per component

    #pragma unroll
    for (int c = 0; c < 4; ++c) {
        float v0 = vin0[c], v1 = vin1[c], v2 = vin2[c], v3 = vin3[c];
        float p  = pin[c];

        // Stable descending ranks (tie-correct selection mask).
        int r0 = 0, r1 = 0, r2 = 0, r3 = 0;
        if (v0 >= v1) r1++; else r0++;
        if (v0 >= v2) r2++; else r0++;
        if (v0 >= v3) r3++; else r0++;
        if (v1 >= v2) r2++; else r1++;
        if (v1 >= v3) r3++; else r1++;
        if (v2 >= v3) r3++; else r2++;

        // Sorted descending values via min/max network (value-identical to
        // stable sort; ties yield equal floats).
        float a = fmaxf(v0, v1), bb = fminf(v0, v1);
        float cc = fmaxf(v2, v3), d = fminf(v2, v3);
        float sv0 = fmaxf(a, cc);
        float sv3 = fminf(bb, d);
        float e = fminf(a, cc), f = fmaxf(bb, d);
        float sv1 = fmaxf(e, f);
        float sv2 = fminf(e, f);

        // Cumsum in rank order (matches jnp.cumsum rounding), + x1, exact div.
        float c0 = sv0;
        float c1 = c0 + sv1;
        float c2 = c1 + sv2;
        float c3 = c2 + sv3;
        float a0 = __fdiv_rn(c0 + p, 2.0f);
        float a1 = __fdiv_rn(c1 + p, 3.0f);
        float a2 = __fdiv_rn(c2 + p, 4.0f);
        float a3 = __fdiv_rn(c3 + p, 5.0f);

        // First-occurrence argmax (jnp.argmax semantics).
        float m = a0; int k = 0;
        if (a1 > m) { m = a1; k = 1; }
        if (a2 > m) { m = a2; k = 2; }
        if (a3 > m) { m = a3; k = 3; }

        float fr = (k == 0) ? 0.5f
                 : (k == 1) ? (2.0f / 3.0f)
                 : (k == 2) ? 0.75f
                 : 0.8f;

        o0[0][c] = (r0 <= k) ? m : v0;
        o0[1][c] = (r1 <= k) ? m : v1;
        o0[2][c] = (r2 <= k) ? m : v2;
        o0[3][c] = (r3 <= k) ? m : v3;

        o2[0][c] = (r0 <= k) ? fr : 1.0f;
        o2[1][c] = (r1 <= k) ? fr : 1.0f;
        o2[2][c] = (r2 <= k) ? fr : 1.0f;
        o2[3][c] = (r3 <= k) ? fr : 1.0f;

        rp[c] = m;
    }

    float* o0b = out0 + base0;
    stcs4(o0b,                  make_float4(o0[0][0], o0[0][1], o0[0][2], o0[0][3]));
    stcs4(o0b + NC,             make_float4(o0[1][0], o0[1][1], o0[1][2], o0[1][3]));
    stcs4(o0b + ROWSTRIDE,      make_float4(o0[2][0], o0[2][1], o0[2][2], o0[2][3]));
    stcs4(o0b + ROWSTRIDE + NC, make_float4(o0[3][0], o0[3][1], o0[3][2], o0[3][3]));

    stcs4(out1 + base1, make_float4(rp[0], rp[1], rp[2], rp[3]));

    float* o2b = out2 + base0;
    stcs4(o2b,                  make_float4(o2[0][0], o2[0][1], o2[0][2], o2[0][3]));
    stcs4(o2b + NC,             make_float4(o2[1][0], o2[1][1], o2[1][2], o2[1][3]));
    stcs4(o2b + ROWSTRIDE,      make_float4(o2[2][0], o2[2][1], o2[2][2], o2[2][3]));
    stcs4(o2b + ROWSTRIDE + NC, make_float4(o2[3][0], o2[3][1], o2[3][2], o2[3][3]));
}

extern "C" void kernel_launch(void* const* d_in, const int* in_sizes, int n_in,
                              void* d_out, int out_size)
{
    const float* x0 = (const float*)d_in[0];
    const float* x1 = (const float*)d_in[1];
    float* out0 = (float*)d_out;
    float* out1 = out0 + (size_t)N_FULL;
    float* out2 = out1 + (size_t)N_POOL;

    const int threads = 256;
    const int blocks = N_THREADS / threads;  // 8192, exact
    unpool_ls_kernel<<<blocks, threads>>>(x0, x1, out0, out1, out2);
}